// round 15
// baseline (speedup 1.0000x reference)
#include <cuda_runtime.h>
#include <cuda_bf16.h>
#include <cuda_fp16.h>
#include <cstdint>

// Problem constants
#define BHN 64          // B*H
#define TT 1024         // sequence length
#define DD 128          // head dim
static __device__ __constant__ float INV_TEMP = 0.08838834764831845f;  // 1/sqrt(128)

// ---------------------------------------------------------------------------
// Scratch.
// ---------------------------------------------------------------------------
__device__ __align__(16) unsigned char g_qf[(size_t)BHN * TT * DD * 2];  // [bh][t][d] fp16 (scaled)
__device__ __align__(16) unsigned char g_kf[(size_t)BHN * TT * DD * 2];  // [bh][t][d] fp16
__device__ __align__(16) unsigned char g_vf[(size_t)BHN * DD * TT * 2];  // [bh][d][t] fp16
__device__ __align__(16) unsigned char g_fh[(size_t)BHN * DD * DD * 2];  // [bh][e][d] bf16 hi
__device__ __align__(16) unsigned char g_fl[(size_t)BHN * DD * DD * 2];  // bf16 lo

typedef unsigned long long u64t;

// ---------------------------------------------------------------------------
// helpers
// ---------------------------------------------------------------------------
__device__ __forceinline__ uint32_t smem_u32(const void* p) {
    uint32_t a;
    asm("{ .reg .u64 t; cvta.to.shared.u64 t, %1; cvt.u32.u64 %0, t; }" : "=r"(a) : "l"(p));
    return a;
}
__device__ __forceinline__ uint32_t pack_bf2(float lo, float hi) {
    uint32_t r;
    asm("cvt.rn.bf16x2.f32 %0, %1, %2;" : "=r"(r) : "f"(hi), "f"(lo));
    return r;
}
__device__ __forceinline__ uint32_t pack_f16(float lo, float hi) {
    uint32_t r;
    asm("cvt.rn.f16x2.f32 %0, %1, %2;" : "=r"(r) : "f"(hi), "f"(lo));
    return r;
}
__device__ __forceinline__ void split2(float v0, float v1, uint32_t& hp, uint32_t& lp) {
    hp = pack_bf2(v0, v1);
    float h0 = __uint_as_float(hp << 16);
    float h1 = __uint_as_float(hp & 0xFFFF0000u);
    lp = pack_bf2(v0 - h0, v1 - h1);
}
__device__ __forceinline__ void ldsm4(uint32_t addr, uint32_t r[4]) {
    asm volatile("ldmatrix.sync.aligned.m8n8.x4.shared.b16 {%0,%1,%2,%3}, [%4];"
        : "=r"(r[0]), "=r"(r[1]), "=r"(r[2]), "=r"(r[3]) : "r"(addr));
}
__device__ __forceinline__ void mma16816(float c[4], const uint32_t a[4],
                                         uint32_t b0, uint32_t b1) {
    asm volatile("mma.sync.aligned.m16n8k16.row.col.f32.bf16.bf16.f32 "
        "{%0,%1,%2,%3}, {%4,%5,%6,%7}, {%8,%9}, {%0,%1,%2,%3};"
        : "+f"(c[0]), "+f"(c[1]), "+f"(c[2]), "+f"(c[3])
        : "r"(a[0]), "r"(a[1]), "r"(a[2]), "r"(a[3]), "r"(b0), "r"(b1));
}
__device__ __forceinline__ void mma16816h(float c[4], const uint32_t a[4],
                                          uint32_t b0, uint32_t b1) {
    asm volatile("mma.sync.aligned.m16n8k16.row.col.f32.f16.f16.f32 "
        "{%0,%1,%2,%3}, {%4,%5,%6,%7}, {%8,%9}, {%0,%1,%2,%3};"
        : "+f"(c[0]), "+f"(c[1]), "+f"(c[2]), "+f"(c[3])
        : "r"(a[0]), "r"(a[1]), "r"(a[2]), "r"(a[3]), "r"(b0), "r"(b1));
}
__device__ __forceinline__ void cpasync16(uint32_t dst, const void* src) {
    asm volatile("cp.async.cg.shared.global [%0], [%1], 16;" :: "r"(dst), "l"(src));
}
#define CP_COMMIT() asm volatile("cp.async.commit_group;" ::: "memory")
#define CP_WAIT2()  asm volatile("cp.async.wait_group 2;" ::: "memory")
#define CP_WAIT1()  asm volatile("cp.async.wait_group 1;" ::: "memory")
#define CP_WAIT0()  asm volatile("cp.async.wait_group 0;" ::: "memory")

// TILE64 : [rows][64 halves], row 128B.  TILE128: [rows][128 halves], row 256B.
__device__ __forceinline__ uint32_t a64(uint32_t base, int fr, int ksi,
                                        int rA, int xr, int kq) {
    return base + (uint32_t)((fr + rA) * 128 + (((ksi * 2 + kq) ^ xr) << 4));
}
__device__ __forceinline__ uint32_t a128(uint32_t base, int fr, int ksi,
                                         int rA, int xr, int kq) {
    return base + (uint32_t)((fr + rA) * 256 + (((ksi * 2 + kq) ^ xr) << 4));
}
__device__ __forceinline__ uint32_t SWZ64(int row, int k) {
    return (uint32_t)(row * 128 + ((((k >> 3) ^ (row & 7)) << 4)) + ((k & 7) << 1));
}
__device__ __forceinline__ uint32_t SWZ128(int row, int k) {
    return (uint32_t)(row * 256 + ((((k >> 3) ^ (row & 7)) << 4)) + ((k & 7) << 1));
}

// loaders (512-thread blocks)
__device__ __forceinline__ void ld_t128r64_512(uint32_t dst, const unsigned char* src,
                                               int stride, int tid) {
    #pragma unroll
    for (int i = 0; i < 2; i++) {
        int idx = i * 512 + tid;
        int row = idx >> 4, ch = idx & 15;
        cpasync16(dst + row * 256 + (((ch ^ (row & 7)) & 15) << 4),
                  src + (size_t)row * stride + ch * 16);
    }
}
__device__ __forceinline__ void ld_t64r128_512(uint32_t dst, const unsigned char* src,
                                               int stride, int tid) {
    #pragma unroll
    for (int i = 0; i < 2; i++) {
        int idx = i * 512 + tid;
        int row = idx >> 3, ch = idx & 7;
        cpasync16(dst + row * 128 + ((ch ^ (row & 7)) << 4),
                  src + (size_t)row * stride + ch * 16);
    }
}
__device__ __forceinline__ void ld_t128r128_512(uint32_t dst, const unsigned char* src,
                                                int stride, int tid) {
    #pragma unroll
    for (int i = 0; i < 4; i++) {
        int idx = i * 512 + tid;
        int row = idx >> 4, ch = idx & 15;
        cpasync16(dst + row * 256 + (((ch ^ (row & 7)) & 15) << 4),
                  src + (size_t)row * stride + ch * 16);
    }
}

// ---------------------------------------------------------------------------
// Prep kernels
// ---------------------------------------------------------------------------
__global__ void qk_f16_kernel(const float* __restrict__ q, const float* __restrict__ k) {
    const bool isq = (blockIdx.y == 0);
    const float* src = isq ? q : k;
    unsigned char* dst = isq ? g_qf : g_kf;
    const float scale = isq ? INV_TEMP : 1.0f;
    size_t i4 = (size_t)blockIdx.x * 256 + threadIdx.x;
    float4 v = ((const float4*)src)[i4];
    v.x *= scale; v.y *= scale; v.z *= scale; v.w *= scale;
    ((uint2*)dst)[i4] = make_uint2(pack_f16(v.x, v.y), pack_f16(v.z, v.w));
}

__global__ void v_f16_T_kernel(const float* __restrict__ v) {
    __shared__ float tile[32][33];
    const int t0 = blockIdx.x * 32;
    const int bh = blockIdx.y;
    const float* src = v + (size_t)bh * TT * DD;
    unsigned char* dv = g_vf + (size_t)bh * DD * TT * 2;
    const int tid = threadIdx.x;
    for (int d0 = 0; d0 < DD; d0 += 32) {
        #pragma unroll
        for (int i = 0; i < 4; i++) {
            int idx = i * 256 + tid;
            int r = idx >> 5, c = idx & 31;
            tile[r][c] = src[(size_t)(t0 + r) * DD + d0 + c];
        }
        __syncthreads();
        #pragma unroll
        for (int i = 0; i < 2; i++) {
            int idx = i * 256 + tid;
            int r = idx >> 4, c2 = (idx & 15) * 2;
            uint32_t p = pack_f16(tile[c2][r], tile[c2 + 1][r]);
            *(uint32_t*)(dv + ((size_t)(d0 + r) * TT + t0 + c2) * 2) = p;
        }
        __syncthreads();
    }
}

// ---------------------------------------------------------------------------
// Feature attention (CUDA-core f32x2) — now also emits transposed split-bf16
// F^T directly (g_fh/g_fl), eliminating the separate transpose kernel.
// ---------------------------------------------------------------------------
__device__ __forceinline__ u64t pk2(float lo, float hi) {
    u64t r; asm("mov.b64 %0, {%1, %2};" : "=l"(r) : "f"(lo), "f"(hi)); return r;
}
__device__ __forceinline__ void fma2(u64t& d, u64t a, u64t b) {
    asm("fma.rn.f32x2 %0, %1, %2, %0;" : "+l"(d) : "l"(a), "l"(b));
}
__device__ __forceinline__ void up2(u64t v, float& a, float& b) {
    asm("mov.b64 {%0, %1}, %2;" : "=f"(a), "=f"(b) : "l"(v));
}

__global__ void __launch_bounds__(256) feature_attn_kernel(
    const float* __restrict__ qf, const float* __restrict__ kf,
    float* __restrict__ attn_f) {
    __shared__ float qs[32 * 34];
    __shared__ float ks[32 * 132];
    __shared__ float Sf[32 * 132];

    const int bh = blockIdx.y;
    const int d0blk = blockIdx.x * 32;
    const float* q = qf + (size_t)bh * TT * DD;
    const float* k = kf + (size_t)bh * TT * DD;
    const int tid = threadIdx.x;
    const int ty = tid >> 4, tx = tid & 15;
    const int r0 = ty * 2;
    const int e0 = tx * 8;

    u64t acc[2][4];
    #pragma unroll
    for (int i = 0; i < 2; i++)
        #pragma unroll
        for (int j = 0; j < 4; j++) acc[i][j] = 0ull;

    for (int tt = 0; tt < TT; tt += 32) {
        #pragma unroll
        for (int i = 0; i < 4; i++) {
            int idx = i * 256 + tid;
            int r = idx >> 5, c = idx & 31;
            qs[r * 34 + c] = q[(size_t)(tt + r) * DD + d0blk + c] * INV_TEMP;
        }
        #pragma unroll
        for (int i = 0; i < 4; i++) {
            int idx = i * 256 + tid;
            int r = idx >> 5, c4 = (idx & 31) * 4;
            *(float4*)&ks[r * 132 + c4] = *(const float4*)&k[(size_t)(tt + r) * DD + c4];
        }
        __syncthreads();
        #pragma unroll 4
        for (int t = 0; t < 32; t++) {
            float2 a = *(float2*)&qs[t * 34 + r0];
            ulonglong2 b0 = *(ulonglong2*)&ks[t * 132 + e0];
            ulonglong2 b1 = *(ulonglong2*)&ks[t * 132 + e0 + 4];
            u64t a0 = pk2(a.x, a.x), a1 = pk2(a.y, a.y);
            fma2(acc[0][0], a0, b0.x); fma2(acc[0][1], a0, b0.y);
            fma2(acc[0][2], a0, b1.x); fma2(acc[0][3], a0, b1.y);
            fma2(acc[1][0], a1, b0.x); fma2(acc[1][1], a1, b0.y);
            fma2(acc[1][2], a1, b1.x); fma2(acc[1][3], a1, b1.y);
        }
        __syncthreads();
    }

    #pragma unroll
    for (int i = 0; i < 2; i++) {
        float x[8];
        up2(acc[i][0], x[0], x[1]); up2(acc[i][1], x[2], x[3]);
        up2(acc[i][2], x[4], x[5]); up2(acc[i][3], x[6], x[7]);
        *(float4*)&Sf[(r0 + i) * 132 + e0]     = make_float4(x[0], x[1], x[2], x[3]);
        *(float4*)&Sf[(r0 + i) * 132 + e0 + 4] = make_float4(x[4], x[5], x[6], x[7]);
    }
    __syncthreads();

    const int lane = tid & 31, w = tid >> 5;
    float* af = attn_f + (size_t)bh * DD * DD;
    #pragma unroll
    for (int rr = 0; rr < 4; rr++) {
        int r = w * 4 + rr;
        float vv[4], mx = -1e30f;
        #pragma unroll
        for (int kk = 0; kk < 4; kk++) {
            vv[kk] = Sf[r * 132 + lane + 32 * kk];
            mx = fmaxf(mx, vv[kk]);
        }
        #pragma unroll
        for (int o = 16; o; o >>= 1) mx = fmaxf(mx, __shfl_xor_sync(~0u, mx, o));
        float ssum = 0.f;
        #pragma unroll
        for (int kk = 0; kk < 4; kk++) { vv[kk] = __expf(vv[kk] - mx); ssum += vv[kk]; }
        #pragma unroll
        for (int o = 16; o; o >>= 1) ssum += __shfl_xor_sync(~0u, ssum, o);
        float iv = 1.0f / ssum;
        #pragma unroll
        for (int kk = 0; kk < 4; kk++) {
            float val = vv[kk] * iv;
            af[(size_t)(d0blk + r) * DD + lane + 32 * kk] = val;
            Sf[r * 132 + lane + 32 * kk] = val;      // keep normalized for transpose
        }
    }
    __syncthreads();

    // transposed split-bf16 output: g_fh/g_fl [bh][e][d0blk + d]
    {
        unsigned char* dh = g_fh + (size_t)bh * DD * DD * 2;
        unsigned char* dl = g_fl + (size_t)bh * DD * DD * 2;
        #pragma unroll
        for (int i = 0; i < 8; i++) {
            int idx = i * 256 + tid;        // 2048 = 128 e x 16 d-pairs
            int e = idx >> 4;
            int d2 = (idx & 15) * 2;
            float v0 = Sf[d2 * 132 + e];
            float v1 = Sf[(d2 + 1) * 132 + e];
            uint32_t hp, lp;
            split2(v0, v1, hp, lp);
            size_t off = ((size_t)e * DD + d0blk + d2) * 2;
            *(uint32_t*)(dh + off) = hp;
            *(uint32_t*)(dl + off) = lp;
        }
    }
}

// ---------------------------------------------------------------------------
// Fused time kernel: 64-row tiles, 512 threads, 2 CTAs/SM.
// Pipelined: iteration c performs MMA1(c), MMA2(c-1), AND epilogue(c) in ONE
// barrier interval (E double-buffered); interval B is only prefetch+commit.
// grid (16, 64), block 512 (16 warps, warp grid 4x4).
// ---------------------------------------------------------------------------
#define SM_Q   0            // Q fp16 TILE128 64 rows, 16K
#define SM_K   16384        // 2 bufs x 16K fp16 (64 t x 128 d)
#define SM_V   49152        // 2 bufs x 16K fp16 (128 d x 64 t)
#define SM_E   81920        // 2 bufs x 8K fp16 (64 t x 64 s)
// tail overlays:
#define SM_TV  0            // tv split-bf16 64 rows: hi @0 16K, lo @16384
#define SM_F   32768        // F^T split-bf16 128 rows: hi @32768 32K, lo @65536
#define SM_RED 98304
#define SM_INV 98560
#define F_SMEM 98816

__global__ void __launch_bounds__(512, 2) fused_time_kernel(
    float* __restrict__ out, float* __restrict__ attn_t) {
    extern __shared__ char sm[];
    const uint32_t sb = smem_u32(sm);
    float* red  = (float*)(sm + SM_RED);
    float* invs = (float*)(sm + SM_INV);

    const int bh = blockIdx.y;
    const int r0 = blockIdx.x * 64;
    const int tid = threadIdx.x;
    const int wid = tid >> 5, lane = tid & 31;
    const int wm = wid & 3, wn = wid >> 2;        // warp grid 4x4
    const int g = lane >> 2, tig = lane & 3;
    const int rA = (lane & 7) + ((lane >> 3) & 1) * 8;
    const int xr = rA & 7, kq = lane >> 4;
    const int fr = wm * 16;

    if (tid < 64) red[tid] = 0.f;

    const unsigned char* qp = g_qf + ((size_t)bh * TT + r0) * 256;
    const unsigned char* kp = g_kf + (size_t)bh * TT * 256;
    const unsigned char* vf = g_vf + (size_t)bh * DD * 2048;
    float* at = attn_t + ((size_t)bh * TT + r0) * TT;

    // prologue groups: G0{Q,K0} G1{V0} G2{K1}
    ld_t128r64_512(sb + SM_Q, qp, 256, tid);
    ld_t128r64_512(sb + SM_K, kp, 256, tid);
    CP_COMMIT();
    ld_t64r128_512(sb + SM_V, vf, 2048, tid);
    CP_COMMIT();
    ld_t128r64_512(sb + SM_K + 16384, kp + 64 * 256, 256, tid);
    CP_COMMIT();

    float rsum[2] = {0, 0};
    float acc2[4][4];
    #pragma unroll
    for (int j = 0; j < 4; j++)
        #pragma unroll
        for (int i = 0; i < 4; i++) acc2[j][i] = 0.f;

    // Pipelined loop: one compute interval holds MMA1(c), MMA2(c-1), epilogue(c).
    for (int c = 0; c <= 16; c++) {
        if (c == 0) { CP_WAIT2(); } else { CP_WAIT1(); }
        __syncthreads();      // K(c), V(c-1) arrived; E(c-1) complete

        if (c < 16) {
            // ---- MMA1(c): scores 64x64, fp16, warp tile 16x16 ----
            float acc1[2][4];
            #pragma unroll
            for (int j = 0; j < 2; j++)
                #pragma unroll
                for (int i = 0; i < 4; i++) acc1[j][i] = 0.f;
            const uint32_t kb = sb + SM_K + (c & 1) * 16384;
            #pragma unroll
            for (int ksi = 0; ksi < 8; ksi++) {
                uint32_t aq[4], bk[4];
                ldsm4(a128(sb + SM_Q, fr, ksi, rA, xr, kq), aq);
                ldsm4(a128(kb, wn * 16, ksi, rA, xr, kq), bk);
                mma16816h(acc1[0], aq, bk[0], bk[2]);
                mma16816h(acc1[1], aq, bk[1], bk[3]);
            }
            // ---- epilogue(c): exp -> unnormalized attn_t + E(c) smem ----
            const uint32_t eb = sb + SM_E + (c & 1) * 8192;
            const int row = fr + g;
            #pragma unroll
            for (int j = 0; j < 2; j++) {
                float e0 = __expf(acc1[j][0]);
                float e1 = __expf(acc1[j][1]);
                float e2 = __expf(acc1[j][2]);
                float e3 = __expf(acc1[j][3]);
                rsum[0] += e0 + e1;
                rsum[1] += e2 + e3;
                int col = wn * 16 + j * 8 + tig * 2;
                *(float2*)&at[(size_t)row * TT + c * 64 + col]       = make_float2(e0, e1);
                *(float2*)&at[(size_t)(row + 8) * TT + c * 64 + col] = make_float2(e2, e3);
                *(uint32_t*)(sm + (eb - sb) + SWZ64(row, col))     = pack_f16(e0, e1);
                *(uint32_t*)(sm + (eb - sb) + SWZ64(row + 8, col)) = pack_f16(e2, e3);
            }
        }
        if (c > 0) {
            // ---- MMA2(c-1): tv += E(c-1) @ V(c-1), fp16, warp tile 16x32 ----
            const uint32_t vb = sb + SM_V + ((c - 1) & 1) * 16384;
            const uint32_t eb = sb + SM_E + ((c - 1) & 1) * 8192;
            #pragma unroll
            for (int ksi = 0; ksi < 4; ksi++) {
                uint32_t ae[4], b0[4], b1[4];
                ldsm4(a64(eb, fr, ksi, rA, xr, kq), ae);
                {
                    int nr = wn * 32;
                    ldsm4(a64(vb, nr, ksi, rA, xr, kq), b0);
                    ldsm4(a64(vb, nr + 16, ksi, rA, xr, kq), b1);
                }
                mma16816h(acc2[0], ae, b0[0], b0[2]);
                mma16816h(acc2[1], ae, b0[1], b0[3]);
                mma16816h(acc2[2], ae, b1[0], b1[2]);
                mma16816h(acc2[3], ae, b1[1], b1[3]);
            }
        }
        __syncthreads();      // all reads of K(c), V(c-1), E(c-1) done

        // prefetch into freed buffers; exactly one commit per iteration
        if (c < 14)
            ld_t128r64_512(sb + SM_K + (c & 1) * 16384,
                           kp + (size_t)(c + 2) * 64 * 256, 256, tid);
        if (c < 15)
            ld_t64r128_512(sb + SM_V + ((c + 1) & 1) * 16384,
                           vf + (c + 1) * 128, 2048, tid);
        CP_COMMIT();
    }

    // ---- rowsums -> invs ----
    rsum[0] += __shfl_xor_sync(~0u, rsum[0], 1);
    rsum[0] += __shfl_xor_sync(~0u, rsum[0], 2);
    rsum[1] += __shfl_xor_sync(~0u, rsum[1], 1);
    rsum[1] += __shfl_xor_sync(~0u, rsum[1], 2);
    if (tig == 0) {
        atomicAdd(&red[fr + g],     rsum[0]);
        atomicAdd(&red[fr + g + 8], rsum[1]);
    }
    __syncthreads();
    if (tid < 64) invs[tid] = 1.0f / red[tid];
    __syncthreads();

    // ---- F^T loads while we stage tv + normalize attn_t ----
    {
        const unsigned char* fhb = g_fh + (size_t)bh * DD * 256;
        const unsigned char* flb = g_fl + (size_t)bh * DD * 256;
        ld_t128r128_512(sb + SM_F,         fhb, 256, tid);
        ld_t128r128_512(sb + SM_F + 32768, flb, 256, tid);
        CP_COMMIT();
    }
    // stage tv split-bf16 into TV region (64 rows TILE128: hi @SM_TV, lo @+16384)
    {
        const int row = fr + g;
        #pragma unroll
        for (int j = 0; j < 4; j++) {
            int d0v = wn * 32 + j * 8 + tig * 2;
            uint32_t hp, lp;
            split2(acc2[j][0], acc2[j][1], hp, lp);
            *(uint32_t*)(sm + SM_TV + SWZ128(row, d0v)) = hp;
            *(uint32_t*)(sm + SM_TV + 16384 + SWZ128(row, d0v)) = lp;
            split2(acc2[j][2], acc2[j][3], hp, lp);
            *(uint32_t*)(sm + SM_TV + SWZ128(row + 8, d0v)) = hp;
            *(uint32_t*)(sm + SM_TV + 16384 + SWZ128(row + 8, d0v)) = lp;
        }
    }
    // normalize attn_t in place (L2-hot; overlaps with F cp.async)
    {
        float4* at4 = (float4*)at;
        #pragma unroll 4
        for (int it = 0; it < 32; it++) {
            int idx = it * 512 + tid;
            int row = idx >> 8, c4 = idx & 255;
            float iv = invs[row];
            float4 vv = at4[(size_t)row * 256 + c4];
            vv.x *= iv; vv.y *= iv; vv.z *= iv; vv.w *= iv;
            at4[(size_t)row * 256 + c4] = vv;
        }
    }
    CP_WAIT0();
    __syncthreads();

    // ---- GEMM3: out = (tv @ F^T) * inv  (split-bf16) ----
    float acc3[4][4];
    #pragma unroll
    for (int j = 0; j < 4; j++)
        #pragma unroll
        for (int i = 0; i < 4; i++) acc3[j][i] = 0.f;

    #pragma unroll
    for (int ksi = 0; ksi < 8; ksi++) {
        uint32_t ah[4], al[4], b0h[4], b1h[4], b0l[4], b1l[4];
        ldsm4(a128(sb + SM_TV, fr, ksi, rA, xr, kq), ah);
        ldsm4(a128(sb + SM_TV + 16384, fr, ksi, rA, xr, kq), al);
        {
            int nr = wn * 32;
            ldsm4(a128(sb + SM_F, nr, ksi, rA, xr, kq), b0h);
            ldsm4(a128(sb + SM_F, nr + 16, ksi, rA, xr, kq), b1h);
            ldsm4(a128(sb + SM_F + 32768, nr, ksi, rA, xr, kq), b0l);
            ldsm4(a128(sb + SM_F + 32768, nr + 16, ksi, rA, xr, kq), b1l);
        }
        mma16816(acc3[0], ah, b0h[0], b0h[2]);
        mma16816(acc3[1], ah, b0h[1], b0h[3]);
        mma16816(acc3[2], ah, b1h[0], b1h[2]);
        mma16816(acc3[3], ah, b1h[1], b1h[3]);
        mma16816(acc3[0], ah, b0l[0], b0l[2]);
        mma16816(acc3[1], ah, b0l[1], b0l[3]);
        mma16816(acc3[2], ah, b1l[0], b1l[2]);
        mma16816(acc3[3], ah, b1l[1], b1l[3]);
        mma16816(acc3[0], al, b0h[0], b0h[2]);
        mma16816(acc3[1], al, b0h[1], b0h[3]);
        mma16816(acc3[2], al, b1h[0], b1h[2]);
        mma16816(acc3[3], al, b1h[1], b1h[3]);
    }

    float* op = out + ((size_t)bh * TT + r0) * DD;
    {
        const int row = fr + g;
        float iva = invs[row];
        float ivb = invs[row + 8];
        #pragma unroll
        for (int j = 0; j < 4; j++) {
            int e = wn * 32 + j * 8 + tig * 2;
            *(float2*)&op[(size_t)row * DD + e] =
                make_float2(acc3[j][0] * iva, acc3[j][1] * iva);
            *(float2*)&op[(size_t)(row + 8) * DD + e] =
                make_float2(acc3[j][2] * ivb, acc3[j][3] * ivb);
        }
    }
}

// ---------------------------------------------------------------------------
// Launch
// ---------------------------------------------------------------------------
extern "C" void kernel_launch(void* const* d_in, const int* in_sizes, int n_in,
                              void* d_out, int out_size) {
    const float* q_time    = (const float*)d_in[0];
    const float* k_time    = (const float*)d_in[1];
    const float* q_feature = (const float*)d_in[2];
    const float* k_feature = (const float*)d_in[3];
    const float* v         = (const float*)d_in[4];

    float* out    = (float*)d_out;                       // [BH][T][D]
    float* attn_t = out + (size_t)BHN * TT * DD;         // [BH][T][T]
    float* attn_f = attn_t + (size_t)BHN * TT * TT;      // [BH][D][D]

    cudaFuncSetAttribute(fused_time_kernel,
                         cudaFuncAttributeMaxDynamicSharedMemorySize, F_SMEM);

    qk_f16_kernel<<<dim3(8192, 2), 256>>>(q_time, k_time);
    v_f16_T_kernel<<<dim3(32, BHN), 256>>>(v);
    feature_attn_kernel<<<dim3(4, BHN), 256>>>(q_feature, k_feature, attn_f);
    fused_time_kernel<<<dim3(16, BHN), 512, F_SMEM>>>(out, attn_t);
}

// round 16
// speedup vs baseline: 1.0642x; 1.0642x over previous
#include <cuda_runtime.h>
#include <cuda_bf16.h>
#include <cuda_fp16.h>
#include <cstdint>

// Problem constants
#define BHN 64          // B*H
#define TT 1024         // sequence length
#define DD 128          // head dim
static __device__ __constant__ float INV_TEMP = 0.08838834764831845f;  // 1/sqrt(128)

// ---------------------------------------------------------------------------
// Scratch.
// ---------------------------------------------------------------------------
__device__ __align__(16) unsigned char g_qf[(size_t)BHN * TT * DD * 2];  // [bh][t][d] fp16 (scaled)
__device__ __align__(16) unsigned char g_kf[(size_t)BHN * TT * DD * 2];  // [bh][t][d] fp16
__device__ __align__(16) unsigned char g_vf[(size_t)BHN * DD * TT * 2];  // [bh][d][t] fp16
__device__ __align__(16) unsigned char g_fh[(size_t)BHN * DD * DD * 2];  // [bh][e][d] bf16 hi
__device__ __align__(16) unsigned char g_fl[(size_t)BHN * DD * DD * 2];  // bf16 lo

typedef unsigned long long u64t;

// ---------------------------------------------------------------------------
// helpers
// ---------------------------------------------------------------------------
__device__ __forceinline__ uint32_t smem_u32(const void* p) {
    uint32_t a;
    asm("{ .reg .u64 t; cvta.to.shared.u64 t, %1; cvt.u32.u64 %0, t; }" : "=r"(a) : "l"(p));
    return a;
}
__device__ __forceinline__ uint32_t pack_bf2(float lo, float hi) {
    uint32_t r;
    asm("cvt.rn.bf16x2.f32 %0, %1, %2;" : "=r"(r) : "f"(hi), "f"(lo));
    return r;
}
__device__ __forceinline__ uint32_t pack_f16(float lo, float hi) {
    uint32_t r;
    asm("cvt.rn.f16x2.f32 %0, %1, %2;" : "=r"(r) : "f"(hi), "f"(lo));
    return r;
}
__device__ __forceinline__ void split2(float v0, float v1, uint32_t& hp, uint32_t& lp) {
    hp = pack_bf2(v0, v1);
    float h0 = __uint_as_float(hp << 16);
    float h1 = __uint_as_float(hp & 0xFFFF0000u);
    lp = pack_bf2(v0 - h0, v1 - h1);
}
__device__ __forceinline__ void ldsm4(uint32_t addr, uint32_t r[4]) {
    asm volatile("ldmatrix.sync.aligned.m8n8.x4.shared.b16 {%0,%1,%2,%3}, [%4];"
        : "=r"(r[0]), "=r"(r[1]), "=r"(r[2]), "=r"(r[3]) : "r"(addr));
}
__device__ __forceinline__ void mma16816(float c[4], const uint32_t a[4],
                                         uint32_t b0, uint32_t b1) {
    asm volatile("mma.sync.aligned.m16n8k16.row.col.f32.bf16.bf16.f32 "
        "{%0,%1,%2,%3}, {%4,%5,%6,%7}, {%8,%9}, {%0,%1,%2,%3};"
        : "+f"(c[0]), "+f"(c[1]), "+f"(c[2]), "+f"(c[3])
        : "r"(a[0]), "r"(a[1]), "r"(a[2]), "r"(a[3]), "r"(b0), "r"(b1));
}
__device__ __forceinline__ void mma16816h(float c[4], const uint32_t a[4],
                                          uint32_t b0, uint32_t b1) {
    asm volatile("mma.sync.aligned.m16n8k16.row.col.f32.f16.f16.f32 "
        "{%0,%1,%2,%3}, {%4,%5,%6,%7}, {%8,%9}, {%0,%1,%2,%3};"
        : "+f"(c[0]), "+f"(c[1]), "+f"(c[2]), "+f"(c[3])
        : "r"(a[0]), "r"(a[1]), "r"(a[2]), "r"(a[3]), "r"(b0), "r"(b1));
}
__device__ __forceinline__ void cpasync16(uint32_t dst, const void* src) {
    asm volatile("cp.async.cg.shared.global [%0], [%1], 16;" :: "r"(dst), "l"(src));
}
#define CP_COMMIT() asm volatile("cp.async.commit_group;" ::: "memory")
#define CP_WAIT2()  asm volatile("cp.async.wait_group 2;" ::: "memory")
#define CP_WAIT1()  asm volatile("cp.async.wait_group 1;" ::: "memory")
#define CP_WAIT0()  asm volatile("cp.async.wait_group 0;" ::: "memory")

// TILE64 : [rows][64 halves], row 128B.  TILE128: [rows][128 halves], row 256B.
__device__ __forceinline__ uint32_t a64(uint32_t base, int fr, int ksi,
                                        int rA, int xr, int kq) {
    return base + (uint32_t)((fr + rA) * 128 + (((ksi * 2 + kq) ^ xr) << 4));
}
__device__ __forceinline__ uint32_t a128(uint32_t base, int fr, int ksi,
                                         int rA, int xr, int kq) {
    return base + (uint32_t)((fr + rA) * 256 + (((ksi * 2 + kq) ^ xr) << 4));
}
__device__ __forceinline__ uint32_t SWZ64(int row, int k) {
    return (uint32_t)(row * 128 + ((((k >> 3) ^ (row & 7)) << 4)) + ((k & 7) << 1));
}
__device__ __forceinline__ uint32_t SWZ128(int row, int k) {
    return (uint32_t)(row * 256 + ((((k >> 3) ^ (row & 7)) << 4)) + ((k & 7) << 1));
}

// loaders (512-thread blocks)
__device__ __forceinline__ void ld_t128r64_512(uint32_t dst, const unsigned char* src,
                                               int stride, int tid) {
    #pragma unroll
    for (int i = 0; i < 2; i++) {
        int idx = i * 512 + tid;
        int row = idx >> 4, ch = idx & 15;
        cpasync16(dst + row * 256 + (((ch ^ (row & 7)) & 15) << 4),
                  src + (size_t)row * stride + ch * 16);
    }
}
__device__ __forceinline__ void ld_t64r128_512(uint32_t dst, const unsigned char* src,
                                               int stride, int tid) {
    #pragma unroll
    for (int i = 0; i < 2; i++) {
        int idx = i * 512 + tid;
        int row = idx >> 3, ch = idx & 7;
        cpasync16(dst + row * 128 + ((ch ^ (row & 7)) << 4),
                  src + (size_t)row * stride + ch * 16);
    }
}
__device__ __forceinline__ void ld_t128r128_512(uint32_t dst, const unsigned char* src,
                                                int stride, int tid) {
    #pragma unroll
    for (int i = 0; i < 4; i++) {
        int idx = i * 512 + tid;
        int row = idx >> 4, ch = idx & 15;
        cpasync16(dst + row * 256 + (((ch ^ (row & 7)) & 15) << 4),
                  src + (size_t)row * stride + ch * 16);
    }
}

// ---------------------------------------------------------------------------
// Prep kernels
// ---------------------------------------------------------------------------
__global__ void qk_f16_kernel(const float* __restrict__ q, const float* __restrict__ k) {
    const bool isq = (blockIdx.y == 0);
    const float* src = isq ? q : k;
    unsigned char* dst = isq ? g_qf : g_kf;
    const float scale = isq ? INV_TEMP : 1.0f;
    size_t i4 = (size_t)blockIdx.x * 256 + threadIdx.x;
    float4 v = ((const float4*)src)[i4];
    v.x *= scale; v.y *= scale; v.z *= scale; v.w *= scale;
    ((uint2*)dst)[i4] = make_uint2(pack_f16(v.x, v.y), pack_f16(v.z, v.w));
}

__global__ void v_f16_T_kernel(const float* __restrict__ v) {
    __shared__ float tile[32][33];
    const int t0 = blockIdx.x * 32;
    const int bh = blockIdx.y;
    const float* src = v + (size_t)bh * TT * DD;
    unsigned char* dv = g_vf + (size_t)bh * DD * TT * 2;
    const int tid = threadIdx.x;
    for (int d0 = 0; d0 < DD; d0 += 32) {
        #pragma unroll
        for (int i = 0; i < 4; i++) {
            int idx = i * 256 + tid;
            int r = idx >> 5, c = idx & 31;
            tile[r][c] = src[(size_t)(t0 + r) * DD + d0 + c];
        }
        __syncthreads();
        #pragma unroll
        for (int i = 0; i < 2; i++) {
            int idx = i * 256 + tid;
            int r = idx >> 4, c2 = (idx & 15) * 2;
            uint32_t p = pack_f16(tile[c2][r], tile[c2 + 1][r]);
            *(uint32_t*)(dv + ((size_t)(d0 + r) * TT + t0 + c2) * 2) = p;
        }
        __syncthreads();
    }
}

// ---------------------------------------------------------------------------
// Feature attention (CUDA-core f32x2) — also emits transposed split-bf16 F^T.
// ---------------------------------------------------------------------------
__device__ __forceinline__ u64t pk2(float lo, float hi) {
    u64t r; asm("mov.b64 %0, {%1, %2};" : "=l"(r) : "f"(lo), "f"(hi)); return r;
}
__device__ __forceinline__ void fma2(u64t& d, u64t a, u64t b) {
    asm("fma.rn.f32x2 %0, %1, %2, %0;" : "+l"(d) : "l"(a), "l"(b));
}
__device__ __forceinline__ void up2(u64t v, float& a, float& b) {
    asm("mov.b64 {%0, %1}, %2;" : "=f"(a), "=f"(b) : "l"(v));
}

__global__ void __launch_bounds__(256) feature_attn_kernel(
    const float* __restrict__ qf, const float* __restrict__ kf,
    float* __restrict__ attn_f) {
    __shared__ float qs[32 * 34];
    __shared__ float ks[32 * 132];
    __shared__ float Sf[32 * 132];

    const int bh = blockIdx.y;
    const int d0blk = blockIdx.x * 32;
    const float* q = qf + (size_t)bh * TT * DD;
    const float* k = kf + (size_t)bh * TT * DD;
    const int tid = threadIdx.x;
    const int ty = tid >> 4, tx = tid & 15;
    const int r0 = ty * 2;
    const int e0 = tx * 8;

    u64t acc[2][4];
    #pragma unroll
    for (int i = 0; i < 2; i++)
        #pragma unroll
        for (int j = 0; j < 4; j++) acc[i][j] = 0ull;

    for (int tt = 0; tt < TT; tt += 32) {
        #pragma unroll
        for (int i = 0; i < 4; i++) {
            int idx = i * 256 + tid;
            int r = idx >> 5, c = idx & 31;
            qs[r * 34 + c] = q[(size_t)(tt + r) * DD + d0blk + c] * INV_TEMP;
        }
        #pragma unroll
        for (int i = 0; i < 4; i++) {
            int idx = i * 256 + tid;
            int r = idx >> 5, c4 = (idx & 31) * 4;
            *(float4*)&ks[r * 132 + c4] = *(const float4*)&k[(size_t)(tt + r) * DD + c4];
        }
        __syncthreads();
        #pragma unroll 4
        for (int t = 0; t < 32; t++) {
            float2 a = *(float2*)&qs[t * 34 + r0];
            ulonglong2 b0 = *(ulonglong2*)&ks[t * 132 + e0];
            ulonglong2 b1 = *(ulonglong2*)&ks[t * 132 + e0 + 4];
            u64t a0 = pk2(a.x, a.x), a1 = pk2(a.y, a.y);
            fma2(acc[0][0], a0, b0.x); fma2(acc[0][1], a0, b0.y);
            fma2(acc[0][2], a0, b1.x); fma2(acc[0][3], a0, b1.y);
            fma2(acc[1][0], a1, b0.x); fma2(acc[1][1], a1, b0.y);
            fma2(acc[1][2], a1, b1.x); fma2(acc[1][3], a1, b1.y);
        }
        __syncthreads();
    }

    #pragma unroll
    for (int i = 0; i < 2; i++) {
        float x[8];
        up2(acc[i][0], x[0], x[1]); up2(acc[i][1], x[2], x[3]);
        up2(acc[i][2], x[4], x[5]); up2(acc[i][3], x[6], x[7]);
        *(float4*)&Sf[(r0 + i) * 132 + e0]     = make_float4(x[0], x[1], x[2], x[3]);
        *(float4*)&Sf[(r0 + i) * 132 + e0 + 4] = make_float4(x[4], x[5], x[6], x[7]);
    }
    __syncthreads();

    const int lane = tid & 31, w = tid >> 5;
    float* af = attn_f + (size_t)bh * DD * DD;
    #pragma unroll
    for (int rr = 0; rr < 4; rr++) {
        int r = w * 4 + rr;
        float vv[4], mx = -1e30f;
        #pragma unroll
        for (int kk = 0; kk < 4; kk++) {
            vv[kk] = Sf[r * 132 + lane + 32 * kk];
            mx = fmaxf(mx, vv[kk]);
        }
        #pragma unroll
        for (int o = 16; o; o >>= 1) mx = fmaxf(mx, __shfl_xor_sync(~0u, mx, o));
        float ssum = 0.f;
        #pragma unroll
        for (int kk = 0; kk < 4; kk++) { vv[kk] = __expf(vv[kk] - mx); ssum += vv[kk]; }
        #pragma unroll
        for (int o = 16; o; o >>= 1) ssum += __shfl_xor_sync(~0u, ssum, o);
        float iv = 1.0f / ssum;
        #pragma unroll
        for (int kk = 0; kk < 4; kk++) {
            float val = vv[kk] * iv;
            af[(size_t)(d0blk + r) * DD + lane + 32 * kk] = val;
            Sf[r * 132 + lane + 32 * kk] = val;      // keep normalized for transpose
        }
    }
    __syncthreads();

    // transposed split-bf16 output: g_fh/g_fl [bh][e][d0blk + d]
    {
        unsigned char* dh = g_fh + (size_t)bh * DD * DD * 2;
        unsigned char* dl = g_fl + (size_t)bh * DD * DD * 2;
        #pragma unroll
        for (int i = 0; i < 8; i++) {
            int idx = i * 256 + tid;        // 2048 = 128 e x 16 d-pairs
            int e = idx >> 4;
            int d2 = (idx & 15) * 2;
            float v0 = Sf[d2 * 132 + e];
            float v1 = Sf[(d2 + 1) * 132 + e];
            uint32_t hp, lp;
            split2(v0, v1, hp, lp);
            size_t off = ((size_t)e * DD + d0blk + d2) * 2;
            *(uint32_t*)(dh + off) = hp;
            *(uint32_t*)(dl + off) = lp;
        }
    }
}

// ---------------------------------------------------------------------------
// Fused time kernel: 64-row tiles, 512 threads, 2 CTAs/SM, R14 pipelining
// (MMA1(c) + MMA2(c-1) in interval A; epilogue(c) in interval B) PLUS
// deferred COALESCED attn_t store: epilogue writes E only to smem; the f32
// attn_t write for chunk c-1 happens in interval A via contiguous STG.128.
// grid (16, 64), block 512 (16 warps, warp grid 4x4).
// ---------------------------------------------------------------------------
#define SM_Q   0            // Q fp16 TILE128 64 rows, 16K
#define SM_K   16384        // 2 bufs x 16K fp16 (64 t x 128 d)
#define SM_V   49152        // 2 bufs x 16K fp16 (128 d x 64 t)
#define SM_E   81920        // 2 bufs x 8K fp16 (64 t x 64 s)
// tail overlays:
#define SM_TV  0            // tv split-bf16 64 rows: hi @0 16K, lo @16384
#define SM_F   32768        // F^T split-bf16 128 rows: hi @32768 32K, lo @65536
#define SM_RED 98304
#define SM_INV 98560
#define F_SMEM 98816

__global__ void __launch_bounds__(512, 2) fused_time_kernel(
    float* __restrict__ out, float* __restrict__ attn_t) {
    extern __shared__ char sm[];
    const uint32_t sb = smem_u32(sm);
    float* red  = (float*)(sm + SM_RED);
    float* invs = (float*)(sm + SM_INV);

    const int bh = blockIdx.y;
    const int r0 = blockIdx.x * 64;
    const int tid = threadIdx.x;
    const int wid = tid >> 5, lane = tid & 31;
    const int wm = wid & 3, wn = wid >> 2;        // warp grid 4x4
    const int g = lane >> 2, tig = lane & 3;
    const int rA = (lane & 7) + ((lane >> 3) & 1) * 8;
    const int xr = rA & 7, kq = lane >> 4;
    const int fr = wm * 16;
    // deferred-store mapping: thread -> (row, 8 contiguous cols)
    const int st_row = tid >> 3;
    const int st_c8  = (tid & 7) * 8;

    if (tid < 64) red[tid] = 0.f;

    const unsigned char* qp = g_qf + ((size_t)bh * TT + r0) * 256;
    const unsigned char* kp = g_kf + (size_t)bh * TT * 256;
    const unsigned char* vf = g_vf + (size_t)bh * DD * 2048;
    float* at = attn_t + ((size_t)bh * TT + r0) * TT;

    // prologue groups: G0{Q,K0} G1{V0} G2{K1}
    ld_t128r64_512(sb + SM_Q, qp, 256, tid);
    ld_t128r64_512(sb + SM_K, kp, 256, tid);
    CP_COMMIT();
    ld_t64r128_512(sb + SM_V, vf, 2048, tid);
    CP_COMMIT();
    ld_t128r64_512(sb + SM_K + 16384, kp + 64 * 256, 256, tid);
    CP_COMMIT();

    float rsum[2] = {0, 0};
    float acc1[2][4];
    float acc2[4][4];
    #pragma unroll
    for (int j = 0; j < 4; j++)
        #pragma unroll
        for (int i = 0; i < 4; i++) acc2[j][i] = 0.f;

    for (int c = 0; c <= 16; c++) {
        if (c == 0) { CP_WAIT2(); } else { CP_WAIT1(); }
        __syncthreads();      // sync1: K(c), V(c-1) arrived; E(c-1) complete

        if (c < 16) {
            // ---- MMA1(c): scores 64x64, fp16, warp tile 16x16 ----
            #pragma unroll
            for (int j = 0; j < 2; j++)
                #pragma unroll
                for (int i = 0; i < 4; i++) acc1[j][i] = 0.f;
            const uint32_t kb = sb + SM_K + (c & 1) * 16384;
            #pragma unroll
            for (int ksi = 0; ksi < 8; ksi++) {
                uint32_t aq[4], bk[4];
                ldsm4(a128(sb + SM_Q, fr, ksi, rA, xr, kq), aq);
                ldsm4(a128(kb, wn * 16, ksi, rA, xr, kq), bk);
                mma16816h(acc1[0], aq, bk[0], bk[2]);
                mma16816h(acc1[1], aq, bk[1], bk[3]);
            }
        }
        if (c > 0) {
            // ---- MMA2(c-1): tv += E(c-1) @ V(c-1), fp16, warp tile 16x32 ----
            const uint32_t vb = sb + SM_V + ((c - 1) & 1) * 16384;
            const uint32_t eb = sb + SM_E + ((c - 1) & 1) * 8192;
            #pragma unroll
            for (int ksi = 0; ksi < 4; ksi++) {
                uint32_t ae[4], b0[4], b1[4];
                ldsm4(a64(eb, fr, ksi, rA, xr, kq), ae);
                {
                    int nr = wn * 32;
                    ldsm4(a64(vb, nr, ksi, rA, xr, kq), b0);
                    ldsm4(a64(vb, nr + 16, ksi, rA, xr, kq), b1);
                }
                mma16816h(acc2[0], ae, b0[0], b0[2]);
                mma16816h(acc2[1], ae, b0[1], b0[3]);
                mma16816h(acc2[2], ae, b1[0], b1[2]);
                mma16816h(acc2[3], ae, b1[1], b1[3]);
            }
            // ---- deferred coalesced attn_t store of chunk c-1 ----
            {
                const uint32_t ebo = SM_E + ((c - 1) & 1) * 8192;
                uint32_t p0 = *(uint32_t*)(sm + ebo + SWZ64(st_row, st_c8));
                uint32_t p1 = *(uint32_t*)(sm + ebo + SWZ64(st_row, st_c8 + 2));
                uint32_t p2 = *(uint32_t*)(sm + ebo + SWZ64(st_row, st_c8 + 4));
                uint32_t p3 = *(uint32_t*)(sm + ebo + SWZ64(st_row, st_c8 + 6));
                float2 f0 = __half22float2(*(__half2*)&p0);
                float2 f1 = __half22float2(*(__half2*)&p1);
                float2 f2 = __half22float2(*(__half2*)&p2);
                float2 f3 = __half22float2(*(__half2*)&p3);
                float* dst = &at[(size_t)st_row * TT + (c - 1) * 64 + st_c8];
                *(float4*)dst       = make_float4(f0.x, f0.y, f1.x, f1.y);
                *(float4*)(dst + 4) = make_float4(f2.x, f2.y, f3.x, f3.y);
            }
        }
        __syncthreads();      // sync2: K(c), V(c-1), E(c-1) consumed

        // prefetch into freed buffers; exactly one commit per iteration
        if (c < 14)
            ld_t128r64_512(sb + SM_K + (c & 1) * 16384,
                           kp + (size_t)(c + 2) * 64 * 256, 256, tid);
        if (c < 15)
            ld_t64r128_512(sb + SM_V + ((c + 1) & 1) * 16384,
                           vf + (c + 1) * 128, 2048, tid);
        CP_COMMIT();

        if (c < 16) {
            // ---- epilogue(c): exp -> rowsums + E(c) fp16 smem only ----
            const uint32_t ebo = SM_E + (c & 1) * 8192;
            const int row = fr + g;
            #pragma unroll
            for (int j = 0; j < 2; j++) {
                float e0 = __expf(acc1[j][0]);
                float e1 = __expf(acc1[j][1]);
                float e2 = __expf(acc1[j][2]);
                float e3 = __expf(acc1[j][3]);
                rsum[0] += e0 + e1;
                rsum[1] += e2 + e3;
                int col = wn * 16 + j * 8 + tig * 2;
                *(uint32_t*)(sm + ebo + SWZ64(row, col))     = pack_f16(e0, e1);
                *(uint32_t*)(sm + ebo + SWZ64(row + 8, col)) = pack_f16(e2, e3);
            }
        }
    }

    // ---- rowsums -> invs ----
    rsum[0] += __shfl_xor_sync(~0u, rsum[0], 1);
    rsum[0] += __shfl_xor_sync(~0u, rsum[0], 2);
    rsum[1] += __shfl_xor_sync(~0u, rsum[1], 1);
    rsum[1] += __shfl_xor_sync(~0u, rsum[1], 2);
    if (tig == 0) {
        atomicAdd(&red[fr + g],     rsum[0]);
        atomicAdd(&red[fr + g + 8], rsum[1]);
    }
    __syncthreads();
    if (tid < 64) invs[tid] = 1.0f / red[tid];
    __syncthreads();

    // ---- F^T loads while we stage tv + normalize attn_t ----
    {
        const unsigned char* fhb = g_fh + (size_t)bh * DD * 256;
        const unsigned char* flb = g_fl + (size_t)bh * DD * 256;
        ld_t128r128_512(sb + SM_F,         fhb, 256, tid);
        ld_t128r128_512(sb + SM_F + 32768, flb, 256, tid);
        CP_COMMIT();
    }
    // stage tv split-bf16 into TV region (64 rows TILE128: hi @SM_TV, lo @+16384)
    {
        const int row = fr + g;
        #pragma unroll
        for (int j = 0; j < 4; j++) {
            int d0v = wn * 32 + j * 8 + tig * 2;
            uint32_t hp, lp;
            split2(acc2[j][0], acc2[j][1], hp, lp);
            *(uint32_t*)(sm + SM_TV + SWZ128(row, d0v)) = hp;
            *(uint32_t*)(sm + SM_TV + 16384 + SWZ128(row, d0v)) = lp;
            split2(acc2[j][2], acc2[j][3], hp, lp);
            *(uint32_t*)(sm + SM_TV + SWZ128(row + 8, d0v)) = hp;
            *(uint32_t*)(sm + SM_TV + 16384 + SWZ128(row + 8, d0v)) = lp;
        }
    }
    // normalize attn_t in place (L2-hot; overlaps with F cp.async)
    {
        float4* at4 = (float4*)at;
        #pragma unroll 4
        for (int it = 0; it < 32; it++) {
            int idx = it * 512 + tid;
            int row = idx >> 8, c4 = idx & 255;
            float iv = invs[row];
            float4 vv = at4[(size_t)row * 256 + c4];
            vv.x *= iv; vv.y *= iv; vv.z *= iv; vv.w *= iv;
            at4[(size_t)row * 256 + c4] = vv;
        }
    }
    CP_WAIT0();
    __syncthreads();

    // ---- GEMM3: out = (tv @ F^T) * inv  (split-bf16) ----
    float acc3[4][4];
    #pragma unroll
    for (int j = 0; j < 4; j++)
        #pragma unroll
        for (int i = 0; i < 4; i++) acc3[j][i] = 0.f;

    #pragma unroll
    for (int ksi = 0; ksi < 8; ksi++) {
        uint32_t ah[4], al[4], b0h[4], b1h[4], b0l[4], b1l[4];
        ldsm4(a128(sb + SM_TV, fr, ksi, rA, xr, kq), ah);
        ldsm4(a128(sb + SM_TV + 16384, fr, ksi, rA, xr, kq), al);
        {
            int nr = wn * 32;
            ldsm4(a128(sb + SM_F, nr, ksi, rA, xr, kq), b0h);
            ldsm4(a128(sb + SM_F, nr + 16, ksi, rA, xr, kq), b1h);
            ldsm4(a128(sb + SM_F + 32768, nr, ksi, rA, xr, kq), b0l);
            ldsm4(a128(sb + SM_F + 32768, nr + 16, ksi, rA, xr, kq), b1l);
        }
        mma16816(acc3[0], ah, b0h[0], b0h[2]);
        mma16816(acc3[1], ah, b0h[1], b0h[3]);
        mma16816(acc3[2], ah, b1h[0], b1h[2]);
        mma16816(acc3[3], ah, b1h[1], b1h[3]);
        mma16816(acc3[0], ah, b0l[0], b0l[2]);
        mma16816(acc3[1], ah, b0l[1], b0l[3]);
        mma16816(acc3[2], ah, b1l[0], b1l[2]);
        mma16816(acc3[3], ah, b1l[1], b1l[3]);
        mma16816(acc3[0], al, b0h[0], b0h[2]);
        mma16816(acc3[1], al, b0h[1], b0h[3]);
        mma16816(acc3[2], al, b1h[0], b1h[2]);
        mma16816(acc3[3], al, b1h[1], b1h[3]);
    }

    float* op = out + ((size_t)bh * TT + r0) * DD;
    {
        const int row = fr + g;
        float iva = invs[row];
        float ivb = invs[row + 8];
        #pragma unroll
        for (int j = 0; j < 4; j++) {
            int e = wn * 32 + j * 8 + tig * 2;
            *(float2*)&op[(size_t)row * DD + e] =
                make_float2(acc3[j][0] * iva, acc3[j][1] * iva);
            *(float2*)&op[(size_t)(row + 8) * DD + e] =
                make_float2(acc3[j][2] * ivb, acc3[j][3] * ivb);
        }
    }
}

// ---------------------------------------------------------------------------
// Launch
// ---------------------------------------------------------------------------
extern "C" void kernel_launch(void* const* d_in, const int* in_sizes, int n_in,
                              void* d_out, int out_size) {
    const float* q_time    = (const float*)d_in[0];
    const float* k_time    = (const float*)d_in[1];
    const float* q_feature = (const float*)d_in[2];
    const float* k_feature = (const float*)d_in[3];
    const float* v         = (const float*)d_in[4];

    float* out    = (float*)d_out;                       // [BH][T][D]
    float* attn_t = out + (size_t)BHN * TT * DD;         // [BH][T][T]
    float* attn_f = attn_t + (size_t)BHN * TT * TT;      // [BH][D][D]

    cudaFuncSetAttribute(fused_time_kernel,
                         cudaFuncAttributeMaxDynamicSharedMemorySize, F_SMEM);

    qk_f16_kernel<<<dim3(8192, 2), 256>>>(q_time, k_time);
    v_f16_T_kernel<<<dim3(32, BHN), 256>>>(v);
    feature_attn_kernel<<<dim3(4, BHN), 256>>>(q_feature, k_feature, attn_f);
    fused_time_kernel<<<dim3(16, BHN), 512, F_SMEM>>>(out, attn_t);
}

// round 17
// speedup vs baseline: 1.4010x; 1.3164x over previous
#include <cuda_runtime.h>
#include <cuda_bf16.h>
#include <cuda_fp16.h>
#include <cstdint>

// Problem constants
#define BHN 64          // B*H
#define TT 1024         // sequence length
#define DD 128          // head dim
static __device__ __constant__ float INV_TEMP = 0.08838834764831845f;  // 1/sqrt(128)

// ---------------------------------------------------------------------------
// Scratch.
// ---------------------------------------------------------------------------
__device__ __align__(16) unsigned char g_qf[(size_t)BHN * TT * DD * 2];  // [bh][t][d] fp16 (scaled)
__device__ __align__(16) unsigned char g_kf[(size_t)BHN * TT * DD * 2];  // [bh][t][d] fp16
__device__ __align__(16) unsigned char g_vf[(size_t)BHN * DD * TT * 2];  // [bh][d][t] fp16
__device__ __align__(16) unsigned char g_fh[(size_t)BHN * DD * DD * 2];  // [bh][e][d] bf16 hi
__device__ __align__(16) unsigned char g_fl[(size_t)BHN * DD * DD * 2];  // bf16 lo
__device__ __align__(16) unsigned char g_ah[(size_t)BHN * DD * TT * 2];  // q_feature^T scaled, bf16 hi [bh][d][t]
__device__ __align__(16) unsigned char g_al[(size_t)BHN * DD * TT * 2];  // bf16 lo
__device__ __align__(16) unsigned char g_bh2[(size_t)BHN * DD * TT * 2]; // k_feature^T bf16 hi [bh][e][t]
__device__ __align__(16) unsigned char g_bl2[(size_t)BHN * DD * TT * 2]; // bf16 lo

typedef unsigned long long u64t;

// ---------------------------------------------------------------------------
// helpers
// ---------------------------------------------------------------------------
__device__ __forceinline__ uint32_t smem_u32(const void* p) {
    uint32_t a;
    asm("{ .reg .u64 t; cvta.to.shared.u64 t, %1; cvt.u32.u64 %0, t; }" : "=r"(a) : "l"(p));
    return a;
}
__device__ __forceinline__ uint32_t pack_bf2(float lo, float hi) {
    uint32_t r;
    asm("cvt.rn.bf16x2.f32 %0, %1, %2;" : "=r"(r) : "f"(hi), "f"(lo));
    return r;
}
__device__ __forceinline__ uint32_t pack_f16(float lo, float hi) {
    uint32_t r;
    asm("cvt.rn.f16x2.f32 %0, %1, %2;" : "=r"(r) : "f"(hi), "f"(lo));
    return r;
}
__device__ __forceinline__ void split2(float v0, float v1, uint32_t& hp, uint32_t& lp) {
    hp = pack_bf2(v0, v1);
    float h0 = __uint_as_float(hp << 16);
    float h1 = __uint_as_float(hp & 0xFFFF0000u);
    lp = pack_bf2(v0 - h0, v1 - h1);
}
__device__ __forceinline__ void ldsm4(uint32_t addr, uint32_t r[4]) {
    asm volatile("ldmatrix.sync.aligned.m8n8.x4.shared.b16 {%0,%1,%2,%3}, [%4];"
        : "=r"(r[0]), "=r"(r[1]), "=r"(r[2]), "=r"(r[3]) : "r"(addr));
}
__device__ __forceinline__ void mma16816(float c[4], const uint32_t a[4],
                                         uint32_t b0, uint32_t b1) {
    asm volatile("mma.sync.aligned.m16n8k16.row.col.f32.bf16.bf16.f32 "
        "{%0,%1,%2,%3}, {%4,%5,%6,%7}, {%8,%9}, {%0,%1,%2,%3};"
        : "+f"(c[0]), "+f"(c[1]), "+f"(c[2]), "+f"(c[3])
        : "r"(a[0]), "r"(a[1]), "r"(a[2]), "r"(a[3]), "r"(b0), "r"(b1));
}
__device__ __forceinline__ void mma16816h(float c[4], const uint32_t a[4],
                                          uint32_t b0, uint32_t b1) {
    asm volatile("mma.sync.aligned.m16n8k16.row.col.f32.f16.f16.f32 "
        "{%0,%1,%2,%3}, {%4,%5,%6,%7}, {%8,%9}, {%0,%1,%2,%3};"
        : "+f"(c[0]), "+f"(c[1]), "+f"(c[2]), "+f"(c[3])
        : "r"(a[0]), "r"(a[1]), "r"(a[2]), "r"(a[3]), "r"(b0), "r"(b1));
}
__device__ __forceinline__ void cpasync16(uint32_t dst, const void* src) {
    asm volatile("cp.async.cg.shared.global [%0], [%1], 16;" :: "r"(dst), "l"(src));
}
#define CP_COMMIT() asm volatile("cp.async.commit_group;" ::: "memory")
#define CP_WAIT2()  asm volatile("cp.async.wait_group 2;" ::: "memory")
#define CP_WAIT1()  asm volatile("cp.async.wait_group 1;" ::: "memory")
#define CP_WAIT0()  asm volatile("cp.async.wait_group 0;" ::: "memory")

// TILE64 : [rows][64 halves], row 128B.  TILE128: [rows][128 halves], row 256B.
__device__ __forceinline__ uint32_t a64(uint32_t base, int fr, int ksi,
                                        int rA, int xr, int kq) {
    return base + (uint32_t)((fr + rA) * 128 + (((ksi * 2 + kq) ^ xr) << 4));
}
__device__ __forceinline__ uint32_t a128(uint32_t base, int fr, int ksi,
                                         int rA, int xr, int kq) {
    return base + (uint32_t)((fr + rA) * 256 + (((ksi * 2 + kq) ^ xr) << 4));
}
__device__ __forceinline__ uint32_t SWZ64(int row, int k) {
    return (uint32_t)(row * 128 + ((((k >> 3) ^ (row & 7)) << 4)) + ((k & 7) << 1));
}
__device__ __forceinline__ uint32_t SWZ128(int row, int k) {
    return (uint32_t)(row * 256 + ((((k >> 3) ^ (row & 7)) << 4)) + ((k & 7) << 1));
}

// loaders (512-thread blocks)
__device__ __forceinline__ void ld_t128r64_512(uint32_t dst, const unsigned char* src,
                                               int stride, int tid) {
    #pragma unroll
    for (int i = 0; i < 2; i++) {
        int idx = i * 512 + tid;
        int row = idx >> 4, ch = idx & 15;
        cpasync16(dst + row * 256 + (((ch ^ (row & 7)) & 15) << 4),
                  src + (size_t)row * stride + ch * 16);
    }
}
__device__ __forceinline__ void ld_t64r128_512(uint32_t dst, const unsigned char* src,
                                               int stride, int tid) {
    #pragma unroll
    for (int i = 0; i < 2; i++) {
        int idx = i * 512 + tid;
        int row = idx >> 3, ch = idx & 7;
        cpasync16(dst + row * 128 + ((ch ^ (row & 7)) << 4),
                  src + (size_t)row * stride + ch * 16);
    }
}
__device__ __forceinline__ void ld_t128r128_512(uint32_t dst, const unsigned char* src,
                                                int stride, int tid) {
    #pragma unroll
    for (int i = 0; i < 4; i++) {
        int idx = i * 512 + tid;
        int row = idx >> 4, ch = idx & 15;
        cpasync16(dst + row * 256 + (((ch ^ (row & 7)) & 15) << 4),
                  src + (size_t)row * stride + ch * 16);
    }
}

// ---------------------------------------------------------------------------
// Prep kernels
// ---------------------------------------------------------------------------
__global__ void qk_f16_kernel(const float* __restrict__ q, const float* __restrict__ k) {
    const bool isq = (blockIdx.y == 0);
    const float* src = isq ? q : k;
    unsigned char* dst = isq ? g_qf : g_kf;
    const float scale = isq ? INV_TEMP : 1.0f;
    size_t i4 = (size_t)blockIdx.x * 256 + threadIdx.x;
    float4 v = ((const float4*)src)[i4];
    v.x *= scale; v.y *= scale; v.z *= scale; v.w *= scale;
    ((uint2*)dst)[i4] = make_uint2(pack_f16(v.x, v.y), pack_f16(v.z, v.w));
}

__global__ void v_f16_T_kernel(const float* __restrict__ v) {
    __shared__ float tile[32][33];
    const int t0 = blockIdx.x * 32;
    const int bh = blockIdx.y;
    const float* src = v + (size_t)bh * TT * DD;
    unsigned char* dv = g_vf + (size_t)bh * DD * TT * 2;
    const int tid = threadIdx.x;
    for (int d0 = 0; d0 < DD; d0 += 32) {
        #pragma unroll
        for (int i = 0; i < 4; i++) {
            int idx = i * 256 + tid;
            int r = idx >> 5, c = idx & 31;
            tile[r][c] = src[(size_t)(t0 + r) * DD + d0 + c];
        }
        __syncthreads();
        #pragma unroll
        for (int i = 0; i < 2; i++) {
            int idx = i * 256 + tid;
            int r = idx >> 4, c2 = (idx & 15) * 2;
            uint32_t p = pack_f16(tile[c2][r], tile[c2 + 1][r]);
            *(uint32_t*)(dv + ((size_t)(d0 + r) * TT + t0 + c2) * 2) = p;
        }
        __syncthreads();
    }
}

// q_feature (scaled) / k_feature -> transposed split-bf16 [bh][d|e][t].
// grid (32, 64, 2), block 256.
__global__ void feat_T_split_kernel(const float* __restrict__ qf,
                                    const float* __restrict__ kf) {
    __shared__ float tile[32][33];
    const int t0 = blockIdx.x * 32;
    const int bh = blockIdx.y;
    const bool isq = (blockIdx.z == 0);
    const float* src = (isq ? qf : kf) + (size_t)bh * TT * DD;
    unsigned char* dh = (isq ? g_ah : g_bh2) + (size_t)bh * DD * TT * 2;
    unsigned char* dl = (isq ? g_al : g_bl2) + (size_t)bh * DD * TT * 2;
    const float scale = isq ? INV_TEMP : 1.0f;
    const int tid = threadIdx.x;
    for (int d0 = 0; d0 < DD; d0 += 32) {
        #pragma unroll
        for (int i = 0; i < 4; i++) {
            int idx = i * 256 + tid;
            int r = idx >> 5, c = idx & 31;
            tile[r][c] = src[(size_t)(t0 + r) * DD + d0 + c] * scale;
        }
        __syncthreads();
        #pragma unroll
        for (int i = 0; i < 2; i++) {
            int idx = i * 256 + tid;
            int r = idx >> 4, c2 = (idx & 15) * 2;
            uint32_t hp, lp;
            split2(tile[c2][r], tile[c2 + 1][r], hp, lp);
            size_t off = ((size_t)(d0 + r) * TT + t0 + c2) * 2;
            *(uint32_t*)(dh + off) = hp;
            *(uint32_t*)(dl + off) = lp;
        }
        __syncthreads();
    }
}

// ---------------------------------------------------------------------------
// Feature attention via mma.sync split-bf16. One CTA per bh, 512 threads.
// scores[d][e] = sum_t A[d][t] * B[e][t]; softmax rows; write attn_f f32 and
// transposed split-bf16 F (g_fh/g_fl).
// smem: 2 bufs x { Ahi 16K | Alo 16K | Bhi 16K | Blo 16K }; Sf overlays after.
// ---------------------------------------------------------------------------
#define FB 65536
#define FA_SMEM 131072

__global__ void __launch_bounds__(512) feature_mma_kernel(float* __restrict__ attn_f) {
    extern __shared__ char sm[];
    const uint32_t sb = smem_u32(sm);
    float* Sf = (float*)sm;                    // [128][132] overlay after mainloop

    const int bh = blockIdx.x;
    const int tid = threadIdx.x;
    const int wid = tid >> 5, lane = tid & 31;
    const int wm = wid & 3, wn = wid >> 2;     // warp grid 4x4, warp tile 32x32
    const int g = lane >> 2, tig = lane & 3;
    const int rA = (lane & 7) + ((lane >> 3) & 1) * 8;
    const int xr = rA & 7, kq = lane >> 4;

    const unsigned char* ahp = g_ah + (size_t)bh * DD * TT * 2;
    const unsigned char* alp = g_al + (size_t)bh * DD * TT * 2;
    const unsigned char* bhp = g_bh2 + (size_t)bh * DD * TT * 2;
    const unsigned char* blp = g_bl2 + (size_t)bh * DD * TT * 2;

    // prologue: chunks 0, 1
    #pragma unroll
    for (int b = 0; b < 2; b++) {
        uint32_t dst = sb + b * FB;
        ld_t64r128_512(dst +     0, ahp + b * 128, 2048, tid);
        ld_t64r128_512(dst + 16384, alp + b * 128, 2048, tid);
        ld_t64r128_512(dst + 32768, bhp + b * 128, 2048, tid);
        ld_t64r128_512(dst + 49152, blp + b * 128, 2048, tid);
        CP_COMMIT();
    }

    float acc[2][4][4];
    #pragma unroll
    for (int mi = 0; mi < 2; mi++)
        #pragma unroll
        for (int nj = 0; nj < 4; nj++)
            #pragma unroll
            for (int i = 0; i < 4; i++) acc[mi][nj][i] = 0.f;

    for (int c = 0; c < 16; c++) {
        CP_WAIT1();
        __syncthreads();
        const uint32_t buf = sb + (c & 1) * FB;
        #pragma unroll
        for (int ksi = 0; ksi < 4; ksi++) {
            uint32_t ah[2][4], al[2][4], b0h[4], b1h[4], b0l[4], b1l[4];
            #pragma unroll
            for (int mi = 0; mi < 2; mi++) {
                ldsm4(a64(buf,         wm * 32 + mi * 16, ksi, rA, xr, kq), ah[mi]);
                ldsm4(a64(buf + 16384, wm * 32 + mi * 16, ksi, rA, xr, kq), al[mi]);
            }
            ldsm4(a64(buf + 32768, wn * 32,      ksi, rA, xr, kq), b0h);
            ldsm4(a64(buf + 32768, wn * 32 + 16, ksi, rA, xr, kq), b1h);
            ldsm4(a64(buf + 49152, wn * 32,      ksi, rA, xr, kq), b0l);
            ldsm4(a64(buf + 49152, wn * 32 + 16, ksi, rA, xr, kq), b1l);
            #pragma unroll
            for (int mi = 0; mi < 2; mi++) {
                mma16816(acc[mi][0], ah[mi], b0h[0], b0h[2]);
                mma16816(acc[mi][1], ah[mi], b0h[1], b0h[3]);
                mma16816(acc[mi][2], ah[mi], b1h[0], b1h[2]);
                mma16816(acc[mi][3], ah[mi], b1h[1], b1h[3]);
                mma16816(acc[mi][0], ah[mi], b0l[0], b0l[2]);
                mma16816(acc[mi][1], ah[mi], b0l[1], b0l[3]);
                mma16816(acc[mi][2], ah[mi], b1l[0], b1l[2]);
                mma16816(acc[mi][3], ah[mi], b1l[1], b1l[3]);
                mma16816(acc[mi][0], al[mi], b0h[0], b0h[2]);
                mma16816(acc[mi][1], al[mi], b0h[1], b0h[3]);
                mma16816(acc[mi][2], al[mi], b1h[0], b1h[2]);
                mma16816(acc[mi][3], al[mi], b1h[1], b1h[3]);
            }
        }
        __syncthreads();
        if (c < 14) {
            uint32_t dst = sb + (c & 1) * FB;
            ld_t64r128_512(dst +     0, ahp + (c + 2) * 128, 2048, tid);
            ld_t64r128_512(dst + 16384, alp + (c + 2) * 128, 2048, tid);
            ld_t64r128_512(dst + 32768, bhp + (c + 2) * 128, 2048, tid);
            ld_t64r128_512(dst + 49152, blp + (c + 2) * 128, 2048, tid);
        }
        CP_COMMIT();
    }
    CP_WAIT0();
    __syncthreads();

    // scores -> Sf [128][132]
    #pragma unroll
    for (int mi = 0; mi < 2; mi++) {
        int row = wm * 32 + mi * 16 + g;
        #pragma unroll
        for (int nj = 0; nj < 4; nj++) {
            int col = wn * 32 + nj * 8 + tig * 2;
            Sf[row * 132 + col]           = acc[mi][nj][0];
            Sf[row * 132 + col + 1]       = acc[mi][nj][1];
            Sf[(row + 8) * 132 + col]     = acc[mi][nj][2];
            Sf[(row + 8) * 132 + col + 1] = acc[mi][nj][3];
        }
    }
    __syncthreads();

    // softmax rows: warp w handles rows w*8 .. w*8+7
    float* af = attn_f + (size_t)bh * DD * DD;
    #pragma unroll
    for (int rr = 0; rr < 8; rr++) {
        int r = wid * 8 + rr;
        float vv[4], mx = -1e30f;
        #pragma unroll
        for (int kk = 0; kk < 4; kk++) {
            vv[kk] = Sf[r * 132 + lane + 32 * kk];
            mx = fmaxf(mx, vv[kk]);
        }
        #pragma unroll
        for (int o = 16; o; o >>= 1) mx = fmaxf(mx, __shfl_xor_sync(~0u, mx, o));
        float ssum = 0.f;
        #pragma unroll
        for (int kk = 0; kk < 4; kk++) { vv[kk] = __expf(vv[kk] - mx); ssum += vv[kk]; }
        #pragma unroll
        for (int o = 16; o; o >>= 1) ssum += __shfl_xor_sync(~0u, ssum, o);
        float iv = 1.0f / ssum;
        #pragma unroll
        for (int kk = 0; kk < 4; kk++) {
            float val = vv[kk] * iv;
            af[(size_t)r * DD + lane + 32 * kk] = val;
            Sf[r * 132 + lane + 32 * kk] = val;
        }
    }
    __syncthreads();

    // transposed split-bf16: g_fh/g_fl [bh][e][d]
    {
        unsigned char* dh = g_fh + (size_t)bh * DD * DD * 2;
        unsigned char* dl = g_fl + (size_t)bh * DD * DD * 2;
        #pragma unroll
        for (int i = 0; i < 16; i++) {
            int idx = i * 512 + tid;        // 128 e x 64 d-pairs
            int e = idx >> 6;
            int d2 = (idx & 63) * 2;
            uint32_t hp, lp;
            split2(Sf[d2 * 132 + e], Sf[(d2 + 1) * 132 + e], hp, lp);
            size_t off = ((size_t)e * DD + d2) * 2;
            *(uint32_t*)(dh + off) = hp;
            *(uint32_t*)(dl + off) = lp;
        }
    }
}

// ---------------------------------------------------------------------------
// Fused time kernel (unchanged from R16 best): 64-row tiles, 512 threads,
// 2 CTAs/SM, pipelined MMA1(c)+MMA2(c-1) with deferred coalesced attn_t store.
// ---------------------------------------------------------------------------
#define SM_Q   0
#define SM_K   16384
#define SM_V   49152
#define SM_E   81920
#define SM_TV  0
#define SM_F   32768
#define SM_RED 98304
#define SM_INV 98560
#define F_SMEM 98816

__global__ void __launch_bounds__(512, 2) fused_time_kernel(
    float* __restrict__ out, float* __restrict__ attn_t) {
    extern __shared__ char sm[];
    const uint32_t sb = smem_u32(sm);
    float* red  = (float*)(sm + SM_RED);
    float* invs = (float*)(sm + SM_INV);

    const int bh = blockIdx.y;
    const int r0 = blockIdx.x * 64;
    const int tid = threadIdx.x;
    const int wid = tid >> 5, lane = tid & 31;
    const int wm = wid & 3, wn = wid >> 2;
    const int g = lane >> 2, tig = lane & 3;
    const int rA = (lane & 7) + ((lane >> 3) & 1) * 8;
    const int xr = rA & 7, kq = lane >> 4;
    const int fr = wm * 16;
    const int st_row = tid >> 3;
    const int st_c8  = (tid & 7) * 8;

    if (tid < 64) red[tid] = 0.f;

    const unsigned char* qp = g_qf + ((size_t)bh * TT + r0) * 256;
    const unsigned char* kp = g_kf + (size_t)bh * TT * 256;
    const unsigned char* vf = g_vf + (size_t)bh * DD * 2048;
    float* at = attn_t + ((size_t)bh * TT + r0) * TT;

    ld_t128r64_512(sb + SM_Q, qp, 256, tid);
    ld_t128r64_512(sb + SM_K, kp, 256, tid);
    CP_COMMIT();
    ld_t64r128_512(sb + SM_V, vf, 2048, tid);
    CP_COMMIT();
    ld_t128r64_512(sb + SM_K + 16384, kp + 64 * 256, 256, tid);
    CP_COMMIT();

    float rsum[2] = {0, 0};
    float acc1[2][4];
    float acc2[4][4];
    #pragma unroll
    for (int j = 0; j < 4; j++)
        #pragma unroll
        for (int i = 0; i < 4; i++) acc2[j][i] = 0.f;

    for (int c = 0; c <= 16; c++) {
        if (c == 0) { CP_WAIT2(); } else { CP_WAIT1(); }
        __syncthreads();

        if (c < 16) {
            #pragma unroll
            for (int j = 0; j < 2; j++)
                #pragma unroll
                for (int i = 0; i < 4; i++) acc1[j][i] = 0.f;
            const uint32_t kb = sb + SM_K + (c & 1) * 16384;
            #pragma unroll
            for (int ksi = 0; ksi < 8; ksi++) {
                uint32_t aq[4], bk[4];
                ldsm4(a128(sb + SM_Q, fr, ksi, rA, xr, kq), aq);
                ldsm4(a128(kb, wn * 16, ksi, rA, xr, kq), bk);
                mma16816h(acc1[0], aq, bk[0], bk[2]);
                mma16816h(acc1[1], aq, bk[1], bk[3]);
            }
        }
        if (c > 0) {
            const uint32_t vb = sb + SM_V + ((c - 1) & 1) * 16384;
            const uint32_t eb = sb + SM_E + ((c - 1) & 1) * 8192;
            #pragma unroll
            for (int ksi = 0; ksi < 4; ksi++) {
                uint32_t ae[4], b0[4], b1[4];
                ldsm4(a64(eb, fr, ksi, rA, xr, kq), ae);
                {
                    int nr = wn * 32;
                    ldsm4(a64(vb, nr, ksi, rA, xr, kq), b0);
                    ldsm4(a64(vb, nr + 16, ksi, rA, xr, kq), b1);
                }
                mma16816h(acc2[0], ae, b0[0], b0[2]);
                mma16816h(acc2[1], ae, b0[1], b0[3]);
                mma16816h(acc2[2], ae, b1[0], b1[2]);
                mma16816h(acc2[3], ae, b1[1], b1[3]);
            }
            {
                const uint32_t ebo = SM_E + ((c - 1) & 1) * 8192;
                uint32_t p0 = *(uint32_t*)(sm + ebo + SWZ64(st_row, st_c8));
                uint32_t p1 = *(uint32_t*)(sm + ebo + SWZ64(st_row, st_c8 + 2));
                uint32_t p2 = *(uint32_t*)(sm + ebo + SWZ64(st_row, st_c8 + 4));
                uint32_t p3 = *(uint32_t*)(sm + ebo + SWZ64(st_row, st_c8 + 6));
                float2 f0 = __half22float2(*(__half2*)&p0);
                float2 f1 = __half22float2(*(__half2*)&p1);
                float2 f2 = __half22float2(*(__half2*)&p2);
                float2 f3 = __half22float2(*(__half2*)&p3);
                float* dst = &at[(size_t)st_row * TT + (c - 1) * 64 + st_c8];
                *(float4*)dst       = make_float4(f0.x, f0.y, f1.x, f1.y);
                *(float4*)(dst + 4) = make_float4(f2.x, f2.y, f3.x, f3.y);
            }
        }
        __syncthreads();

        if (c < 14)
            ld_t128r64_512(sb + SM_K + (c & 1) * 16384,
                           kp + (size_t)(c + 2) * 64 * 256, 256, tid);
        if (c < 15)
            ld_t64r128_512(sb + SM_V + ((c + 1) & 1) * 16384,
                           vf + (c + 1) * 128, 2048, tid);
        CP_COMMIT();

        if (c < 16) {
            const uint32_t ebo = SM_E + (c & 1) * 8192;
            const int row = fr + g;
            #pragma unroll
            for (int j = 0; j < 2; j++) {
                float e0 = __expf(acc1[j][0]);
                float e1 = __expf(acc1[j][1]);
                float e2 = __expf(acc1[j][2]);
                float e3 = __expf(acc1[j][3]);
                rsum[0] += e0 + e1;
                rsum[1] += e2 + e3;
                int col = wn * 16 + j * 8 + tig * 2;
                *(uint32_t*)(sm + ebo + SWZ64(row, col))     = pack_f16(e0, e1);
                *(uint32_t*)(sm + ebo + SWZ64(row + 8, col)) = pack_f16(e2, e3);
            }
        }
    }

    rsum[0] += __shfl_xor_sync(~0u, rsum[0], 1);
    rsum[0] += __shfl_xor_sync(~0u, rsum[0], 2);
    rsum[1] += __shfl_xor_sync(~0u, rsum[1], 1);
    rsum[1] += __shfl_xor_sync(~0u, rsum[1], 2);
    if (tig == 0) {
        atomicAdd(&red[fr + g],     rsum[0]);
        atomicAdd(&red[fr + g + 8], rsum[1]);
    }
    __syncthreads();
    if (tid < 64) invs[tid] = 1.0f / red[tid];
    __syncthreads();

    {
        const unsigned char* fhb = g_fh + (size_t)bh * DD * 256;
        const unsigned char* flb = g_fl + (size_t)bh * DD * 256;
        ld_t128r128_512(sb + SM_F,         fhb, 256, tid);
        ld_t128r128_512(sb + SM_F + 32768, flb, 256, tid);
        CP_COMMIT();
    }
    {
        const int row = fr + g;
        #pragma unroll
        for (int j = 0; j < 4; j++) {
            int d0v = wn * 32 + j * 8 + tig * 2;
            uint32_t hp, lp;
            split2(acc2[j][0], acc2[j][1], hp, lp);
            *(uint32_t*)(sm + SM_TV + SWZ128(row, d0v)) = hp;
            *(uint32_t*)(sm + SM_TV + 16384 + SWZ128(row, d0v)) = lp;
            split2(acc2[j][2], acc2[j][3], hp, lp);
            *(uint32_t*)(sm + SM_TV + SWZ128(row + 8, d0v)) = hp;
            *(uint32_t*)(sm + SM_TV + 16384 + SWZ128(row + 8, d0v)) = lp;
        }
    }
    {
        float4* at4 = (float4*)at;
        #pragma unroll 4
        for (int it = 0; it < 32; it++) {
            int idx = it * 512 + tid;
            int row = idx >> 8, c4 = idx & 255;
            float iv = invs[row];
            float4 vv = at4[(size_t)row * 256 + c4];
            vv.x *= iv; vv.y *= iv; vv.z *= iv; vv.w *= iv;
            at4[(size_t)row * 256 + c4] = vv;
        }
    }
    CP_WAIT0();
    __syncthreads();

    float acc3[4][4];
    #pragma unroll
    for (int j = 0; j < 4; j++)
        #pragma unroll
        for (int i = 0; i < 4; i++) acc3[j][i] = 0.f;

    #pragma unroll
    for (int ksi = 0; ksi < 8; ksi++) {
        uint32_t ah[4], al[4], b0h[4], b1h[4], b0l[4], b1l[4];
        ldsm4(a128(sb + SM_TV, fr, ksi, rA, xr, kq), ah);
        ldsm4(a128(sb + SM_TV + 16384, fr, ksi, rA, xr, kq), al);
        {
            int nr = wn * 32;
            ldsm4(a128(sb + SM_F, nr, ksi, rA, xr, kq), b0h);
            ldsm4(a128(sb + SM_F, nr + 16, ksi, rA, xr, kq), b1h);
            ldsm4(a128(sb + SM_F + 32768, nr, ksi, rA, xr, kq), b0l);
            ldsm4(a128(sb + SM_F + 32768, nr + 16, ksi, rA, xr, kq), b1l);
        }
        mma16816(acc3[0], ah, b0h[0], b0h[2]);
        mma16816(acc3[1], ah, b0h[1], b0h[3]);
        mma16816(acc3[2], ah, b1h[0], b1h[2]);
        mma16816(acc3[3], ah, b1h[1], b1h[3]);
        mma16816(acc3[0], ah, b0l[0], b0l[2]);
        mma16816(acc3[1], ah, b0l[1], b0l[3]);
        mma16816(acc3[2], ah, b1l[0], b1l[2]);
        mma16816(acc3[3], ah, b1l[1], b1l[3]);
        mma16816(acc3[0], al, b0h[0], b0h[2]);
        mma16816(acc3[1], al, b0h[1], b0h[3]);
        mma16816(acc3[2], al, b1h[0], b1h[2]);
        mma16816(acc3[3], al, b1h[1], b1h[3]);
    }

    float* op = out + ((size_t)bh * TT + r0) * DD;
    {
        const int row = fr + g;
        float iva = invs[row];
        float ivb = invs[row + 8];
        #pragma unroll
        for (int j = 0; j < 4; j++) {
            int e = wn * 32 + j * 8 + tig * 2;
            *(float2*)&op[(size_t)row * DD + e] =
                make_float2(acc3[j][0] * iva, acc3[j][1] * iva);
            *(float2*)&op[(size_t)(row + 8) * DD + e] =
                make_float2(acc3[j][2] * ivb, acc3[j][3] * ivb);
        }
    }
}

// ---------------------------------------------------------------------------
// Launch
// ---------------------------------------------------------------------------
extern "C" void kernel_launch(void* const* d_in, const int* in_sizes, int n_in,
                              void* d_out, int out_size) {
    const float* q_time    = (const float*)d_in[0];
    const float* k_time    = (const float*)d_in[1];
    const float* q_feature = (const float*)d_in[2];
    const float* k_feature = (const float*)d_in[3];
    const float* v         = (const float*)d_in[4];

    float* out    = (float*)d_out;                       // [BH][T][D]
    float* attn_t = out + (size_t)BHN * TT * DD;         // [BH][T][T]
    float* attn_f = attn_t + (size_t)BHN * TT * TT;      // [BH][D][D]

    cudaFuncSetAttribute(fused_time_kernel,
                         cudaFuncAttributeMaxDynamicSharedMemorySize, F_SMEM);
    cudaFuncSetAttribute(feature_mma_kernel,
                         cudaFuncAttributeMaxDynamicSharedMemorySize, FA_SMEM);

    qk_f16_kernel<<<dim3(8192, 2), 256>>>(q_time, k_time);
    v_f16_T_kernel<<<dim3(32, BHN), 256>>>(v);
    feat_T_split_kernel<<<dim3(32, BHN, 2), 256>>>(q_feature, k_feature);
    feature_mma_kernel<<<BHN, 512, FA_SMEM>>>(attn_f);
    fused_time_kernel<<<dim3(16, BHN), 512, F_SMEM>>>(out, attn_t);
}